// round 3
// baseline (speedup 1.0000x reference)
#include <cuda_runtime.h>
#include <cuda_bf16.h>

#define B    8
#define C    256
#define HW   65536                 // 256*256 floats per plane
#define HW4  16384                 // float4 per plane
#define F4_PER_BLOCK 512           // 2 float4 per thread * 256 threads
#define BLOCKS_PER_PLANE (HW4 / F4_PER_BLOCK)   // 32

__device__ float g_scale[B * C];   // 1 + softmax weight (scratch; no allocs allowed)

// ---------------------------------------------------------------------------
// Fused gate: MLP (2 layers) + softmax, one kernel.
// grid = 8 (one block per batch row), block = 1024 (32 warps).
// Each warp computes 8 outputs per layer with front-batched coalesced float4
// weight loads (16 independent LDG.128 -> deep MLP, one DRAM latency).
// ---------------------------------------------------------------------------
__global__ void __launch_bounds__(1024) gate_fused(const float* __restrict__ semantic,
                                                   const float* __restrict__ W1,
                                                   const float* __restrict__ b1,
                                                   const float* __restrict__ W2,
                                                   const float* __restrict__ b2) {
    const int b    = blockIdx.x;
    const int tid  = threadIdx.x;
    const int warp = tid >> 5;          // 0..31
    const int lane = tid & 31;

    __shared__ float s_vec[C];          // layer input (semantic, then h)
    __shared__ float s_out[C];          // layer output
    __shared__ float s_red[C];          // softmax reduction

    if (tid < C) s_vec[tid] = semantic[b * C + tid];
    __syncthreads();

    // ---------------- Layer 1: h = leaky_relu(semantic @ W1^T + b1) --------
    {
        const float4 ia = ((const float4*)s_vec)[lane];
        const float4 ib = ((const float4*)s_vec)[lane + 32];
        const int c0 = warp * 8;
        float acc[8];
        #pragma unroll
        for (int j = 0; j < 8; ++j) {
            const float4* w4 = (const float4*)(W1 + (c0 + j) * C);
            float4 wa = __ldg(w4 + lane);
            float4 wb = __ldg(w4 + lane + 32);
            acc[j] = wa.x * ia.x + wa.y * ia.y + wa.z * ia.z + wa.w * ia.w
                   + wb.x * ib.x + wb.y * ib.y + wb.z * ib.z + wb.w * ib.w;
        }
        #pragma unroll
        for (int j = 0; j < 8; ++j) {
            float p = acc[j];
            #pragma unroll
            for (int s = 16; s > 0; s >>= 1) p += __shfl_xor_sync(0xffffffffu, p, s);
            if (lane == 0) {
                float r = p + __ldg(b1 + c0 + j);
                s_out[c0 + j] = r > 0.0f ? r : 0.1f * r;
            }
        }
    }
    __syncthreads();
    if (tid < C) s_vec[tid] = s_out[tid];
    __syncthreads();

    // ---------------- Layer 2: logits = h @ W2^T + b2 ----------------------
    {
        const float4 ia = ((const float4*)s_vec)[lane];
        const float4 ib = ((const float4*)s_vec)[lane + 32];
        const int c0 = warp * 8;
        float acc[8];
        #pragma unroll
        for (int j = 0; j < 8; ++j) {
            const float4* w4 = (const float4*)(W2 + (c0 + j) * C);
            float4 wa = __ldg(w4 + lane);
            float4 wb = __ldg(w4 + lane + 32);
            acc[j] = wa.x * ia.x + wa.y * ia.y + wa.z * ia.z + wa.w * ia.w
                   + wb.x * ib.x + wb.y * ib.y + wb.z * ib.z + wb.w * ib.w;
        }
        #pragma unroll
        for (int j = 0; j < 8; ++j) {
            float p = acc[j];
            #pragma unroll
            for (int s = 16; s > 0; s >>= 1) p += __shfl_xor_sync(0xffffffffu, p, s);
            if (lane == 0) s_out[c0 + j] = p + __ldg(b2 + c0 + j);
        }
    }
    __syncthreads();

    // ---------------- Softmax over the 256 logits --------------------------
    const float logit = (tid < C) ? s_out[tid] : -1e30f;
    if (tid < C) s_red[tid] = logit;
    __syncthreads();
    #pragma unroll
    for (int s = 128; s > 0; s >>= 1) {
        if (tid < s) s_red[tid] = fmaxf(s_red[tid], s_red[tid + s]);
        __syncthreads();
    }
    const float m = s_red[0];
    __syncthreads();
    const float e = (tid < C) ? __expf(logit - m) : 0.0f;
    if (tid < C) s_red[tid] = e;
    __syncthreads();
    #pragma unroll
    for (int s = 128; s > 0; s >>= 1) {
        if (tid < s) s_red[tid] += s_red[tid + s];
        __syncthreads();
    }
    if (tid < C) g_scale[b * C + tid] = 1.0f + e / s_red[0];
}

// ---------------------------------------------------------------------------
// y = x * scale[plane]. 2 float4 per thread, front-batched (MLP_p1 = 2).
// Block covers 512 consecutive float4 of one plane; 32 blocks per plane.
// grid = 65536 blocks. Streaming hints (touch-once data).
// ---------------------------------------------------------------------------
__global__ void __launch_bounds__(256) scale_kernel(const float4* __restrict__ x,
                                                    float4* __restrict__ y) {
    const int blk   = blockIdx.x;
    const int plane = blk >> 5;                       // / BLOCKS_PER_PLANE
    const float s   = __ldg(&g_scale[plane]);
    const size_t i0 = (size_t)blk * F4_PER_BLOCK + threadIdx.x;

    float4 v0 = __ldcs(x + i0);
    float4 v1 = __ldcs(x + i0 + 256);

    v0.x *= s; v0.y *= s; v0.z *= s; v0.w *= s;
    v1.x *= s; v1.y *= s; v1.z *= s; v1.w *= s;

    __stcs(y + i0,       v0);
    __stcs(y + i0 + 256, v1);
}

extern "C" void kernel_launch(void* const* d_in, const int* in_sizes, int n_in,
                              void* d_out, int out_size) {
    const float* x        = (const float*)d_in[0];
    const float* semantic = (const float*)d_in[1];
    const float* W1       = (const float*)d_in[2];
    const float* b1       = (const float*)d_in[3];
    const float* W2       = (const float*)d_in[4];
    const float* b2       = (const float*)d_in[5];
    float* out = (float*)d_out;

    gate_fused<<<B, 1024>>>(semantic, W1, b1, W2, b2);

    const int nblocks = (B * C) * BLOCKS_PER_PLANE;   // 65536
    scale_kernel<<<nblocks, 256>>>((const float4*)x, (float4*)out);
}

// round 4
// speedup vs baseline: 1.0134x; 1.0134x over previous
#include <cuda_runtime.h>
#include <cuda_bf16.h>

#define B    8
#define C    256
#define HW4  16384                 // float4 per (b,c) plane
#define F4_PER_THREAD 4
#define F4_PER_BLOCK  (256 * F4_PER_THREAD)          // 1024
#define BLOCKS_PER_PLANE (HW4 / F4_PER_BLOCK)        // 16

// Scratch (no allocation allowed -> __device__ globals)
__device__ float g_h[B * C];        // hidden layer
__device__ float g_logits[B * C];   // logits
__device__ float g_scale[B * C];    // 1 + softmax weight

// ---------------------------------------------------------------------------
// Warp-per-output matvec: out[b,c] = act( in[b,:] . W[c,:] + bias[c] )
// 256 blocks x 256 threads = 2048 warps = B*C outputs. Coalesced float4 rows.
// ---------------------------------------------------------------------------
template <bool LEAKY>
__global__ void __launch_bounds__(256) matvec_kernel(const float* __restrict__ in,
                                                     const float* __restrict__ W,
                                                     const float* __restrict__ bias,
                                                     float* __restrict__ out) {
    const int warp = (blockIdx.x * blockDim.x + threadIdx.x) >> 5; // 0..2047
    const int lane = threadIdx.x & 31;
    const int b = warp >> 8;        // 0..7
    const int c = warp & 255;       // 0..255

    const float4* __restrict__ w4 = (const float4*)(W + c * C);
    const float4* __restrict__ i4 = (const float4*)(in + b * C);

    float4 wa = __ldg(w4 + lane);
    float4 wb = __ldg(w4 + lane + 32);
    float4 ia = __ldg(i4 + lane);
    float4 ib = __ldg(i4 + lane + 32);

    float p = wa.x * ia.x + wa.y * ia.y + wa.z * ia.z + wa.w * ia.w
            + wb.x * ib.x + wb.y * ib.y + wb.z * ib.z + wb.w * ib.w;

    #pragma unroll
    for (int s = 16; s > 0; s >>= 1)
        p += __shfl_xor_sync(0xffffffffu, p, s);

    if (lane == 0) {
        float r = p + __ldg(bias + c);
        if (LEAKY) r = r > 0.0f ? r : 0.1f * r;
        out[b * C + c] = r;
    }
}

// ---------------------------------------------------------------------------
// Softmax over channels per batch row -> g_scale = 1 + softmax(logits)
// ---------------------------------------------------------------------------
__global__ void softmax_kernel() {
    const int b = blockIdx.x;
    const int c = threadIdx.x;
    __shared__ float red[C];

    const float logit = g_logits[b * C + c];
    red[c] = logit;
    __syncthreads();
    #pragma unroll
    for (int s = 128; s > 0; s >>= 1) {
        if (c < s) red[c] = fmaxf(red[c], red[c + s]);
        __syncthreads();
    }
    const float m = red[0];
    __syncthreads();

    const float e = __expf(logit - m);
    red[c] = e;
    __syncthreads();
    #pragma unroll
    for (int s = 128; s > 0; s >>= 1) {
        if (c < s) red[c] += red[c + s];
        __syncthreads();
    }
    g_scale[b * C + c] = 1.0f + e / red[0];
}

// ---------------------------------------------------------------------------
// y = x * scale[plane]. 4 float4 per thread, front-batched (MLP_p1 = 4).
// Block covers 1024 consecutive float4 of one plane; 16 blocks per plane.
// grid = 32768 blocks. Streaming hints (touch-once data).
// ---------------------------------------------------------------------------
__global__ void __launch_bounds__(256) scale_kernel(const float4* __restrict__ x,
                                                    float4* __restrict__ y) {
    const int blk   = blockIdx.x;
    const int plane = blk >> 4;                      // / BLOCKS_PER_PLANE
    const float s   = __ldg(&g_scale[plane]);
    const size_t i0 = (size_t)blk * F4_PER_BLOCK + threadIdx.x;

    float4 v0 = __ldcs(x + i0);
    float4 v1 = __ldcs(x + i0 + 256);
    float4 v2 = __ldcs(x + i0 + 512);
    float4 v3 = __ldcs(x + i0 + 768);

    v0.x *= s; v0.y *= s; v0.z *= s; v0.w *= s;
    v1.x *= s; v1.y *= s; v1.z *= s; v1.w *= s;
    v2.x *= s; v2.y *= s; v2.z *= s; v2.w *= s;
    v3.x *= s; v3.y *= s; v3.z *= s; v3.w *= s;

    __stcs(y + i0,       v0);
    __stcs(y + i0 + 256, v1);
    __stcs(y + i0 + 512, v2);
    __stcs(y + i0 + 768, v3);
}

extern "C" void kernel_launch(void* const* d_in, const int* in_sizes, int n_in,
                              void* d_out, int out_size) {
    const float* x        = (const float*)d_in[0];
    const float* semantic = (const float*)d_in[1];
    const float* W1       = (const float*)d_in[2];
    const float* b1       = (const float*)d_in[3];
    const float* W2       = (const float*)d_in[4];
    const float* b2       = (const float*)d_in[5];
    float* out = (float*)d_out;

    float* g_h_ptr, *g_logits_ptr;
    cudaGetSymbolAddress((void**)&g_h_ptr, g_h);
    cudaGetSymbolAddress((void**)&g_logits_ptr, g_logits);

    matvec_kernel<true ><<<256, 256>>>(semantic, W1, b1, g_h_ptr);
    matvec_kernel<false><<<256, 256>>>(g_h_ptr, W2, b2, g_logits_ptr);
    softmax_kernel<<<B, C>>>();

    const int nblocks = (B * C) * BLOCKS_PER_PLANE;   // 32768
    scale_kernel<<<nblocks, 256>>>((const float4*)x, (float4*)out);
}